// round 3
// baseline (speedup 1.0000x reference)
#include <cuda_runtime.h>
#include <math.h>

#define H 256
#define W 256
#define NIMG 8              // 4 batches x {true, pred}
#define NW 8                // 256 bits per row
#define NPIX (4*H*W)        // 262144
#define NB 144              // <= 148 SMs -> all blocks co-resident
#define NT 256
#define NTHREADS (NB*NT)    // 36864

// ---------------- device state (self-resetting; initializers = first-run values)
__device__ float    g_pp[NPIX];
__device__ unsigned g_maskb[NIMG][H][NW];
__device__ unsigned g_skelb[NIMG][H][NW];
__device__ float    g_dist[NIMG][H][W];
__device__ unsigned g_rmax[NIMG];                       // 0
__device__ unsigned g_rmin[NIMG] = {0x7f7fffffu,0x7f7fffffu,0x7f7fffffu,0x7f7fffffu,
                                    0x7f7fffffu,0x7f7fffffu,0x7f7fffffu,0x7f7fffffu};
__device__ double   g_sums[4];                          // 0
__device__ int      g_flag[NIMG];                       // 0
__device__ unsigned g_count;                            // 0
__device__ unsigned g_bar;                              // 0

__device__ __forceinline__ void grid_bar(unsigned target) {
    __syncthreads();
    if (threadIdx.x == 0) {
        __threadfence();                       // release my block's writes
        atomicAdd(&g_bar, 1u);
        while (atomicAdd(&g_bar, 0u) < target) { }
        __threadfence();                       // acquire
    }
    __syncthreads();
}

__global__ void __launch_bounds__(NT) k_fused(const float* __restrict__ ypred,
                                              const int*   __restrict__ ytrue,
                                              float*       __restrict__ out) {
    __shared__ union Sh {
        struct { unsigned simg[H][NW]; unsigned shd[H][NW]; } sk;                    // 16KB
        struct { unsigned bits[H][NW]; float shg[16][257]; float sdist[16][257];
                 unsigned skelw[H]; } ed;                                            // ~42KB
    } S;
    __shared__ float s_red[2][8];
    __shared__ float s_rmx[NIMG], s_rmn[NIMG];
    __shared__ float s_w[8][4];

    const int t    = threadIdx.x;
    const int gtid = blockIdx.x * NT + t;

    // ================= Phase A: elementwise + bit packing =================
    for (int idx = gtid; idx < NPIX; idx += NTHREADS) {
        float x  = ypred[idx];
        float p  = __fdividef(1.0f, 1.0f + __expf(-x));
        float pp = __fdividef(1.0f, 1.0f + __expf(1.0f - 2.0f * p));  // softmax ch1
        g_pp[idx] = pp;
        unsigned bp = __ballot_sync(0xffffffffu, x > 0.0f);           // hard = pp>0.5
        unsigned bt = __ballot_sync(0xffffffffu, ytrue[idx] > 0);
        if ((t & 31) == 0 || true) { }                                 // (no-op)
        if (( (idx) & 31) == 0) {
            int b = idx >> 16, row = (idx >> 8) & 255, word = (idx & 255) >> 5;
            g_maskb[b * 2 + 0][row][word] = bt;
            g_maskb[b * 2 + 1][row][word] = bp;
        }
    }
    grid_bar(NB);

    // ================= Phase B =================
    if (blockIdx.x < NIMG) {
        // ---- bitboard skeleton: one block per image, thread = row ----
        int img = blockIdx.x;
        unsigned skel[NW];
        #pragma unroll
        for (int w = 0; w < NW; w++) { S.sk.simg[t][w] = g_maskb[img][t][w]; skel[w] = 0u; }
        __syncthreads();
        for (int it = 0; it < 11; it++) {
            unsigned x[NW], e[NW], vu[NW], vd[NW];
            #pragma unroll
            for (int w = 0; w < NW; w++) x[w] = S.sk.simg[t][w];
            #pragma unroll
            for (int w = 0; w < NW; w++) {
                vu[w] = (t > 0)     ? S.sk.simg[t - 1][w] : 0xffffffffu;
                vd[w] = (t < H - 1) ? S.sk.simg[t + 1][w] : 0xffffffffu;
            }
            #pragma unroll
            for (int w = 0; w < NW; w++) {
                unsigned sl = (x[w] << 1) | ((w > 0)      ? (x[w - 1] >> 31) : 1u);
                unsigned sr = (x[w] >> 1) | ((w < NW - 1) ? (x[w + 1] << 31) : 0x80000000u);
                e[w] = vu[w] & vd[w] & x[w] & sl & sr;
            }
            #pragma unroll
            for (int w = 0; w < NW; w++) {
                unsigned ol  = (e[w] << 1) | ((w > 0)      ? (e[w - 1] >> 31) : 0u);
                unsigned orr = (e[w] >> 1) | ((w < NW - 1) ? (e[w + 1] << 31) : 0u);
                S.sk.shd[t][w] = e[w] | ol | orr;
            }
            __syncthreads();
            #pragma unroll
            for (int w = 0; w < NW; w++) {
                unsigned o = S.sk.shd[t][w];
                if (t > 0)     o |= S.sk.shd[t - 1][w];
                if (t < H - 1) o |= S.sk.shd[t + 1][w];
                skel[w] |= x[w] & ~o;
                S.sk.simg[t][w] = e[w];
            }
            __syncthreads();
        }
        #pragma unroll
        for (int w = 0; w < NW; w++) g_skelb[img][t][w] = skel[w];
        __threadfence();
        __syncthreads();
        if (t == 0) atomicExch(&g_flag[img], 1);          // release skeleton
    } else if (blockIdx.x < NIMG + NIMG * 16) {
        // ---- EDT: one block per (image, 16-col tile) ----
        int bb   = blockIdx.x - NIMG;
        int img  = bb >> 4;
        int tile = bb & 15;                               // cols [tile*16, tile*16+16)

        {   // load full image bitboard (coalesced)
            unsigned* dst = &S.ed.bits[0][0];
            const unsigned* src = &g_maskb[img][0][0];
            for (int j = t; j < H * NW; j += NT) dst[j] = src[j];
        }
        __syncthreads();

        // horizontal EDT via bit scans: thread = row t, 16 cols
        {
            unsigned zeros[NW];
            #pragma unroll
            for (int w = 0; w < NW; w++) zeros[w] = ~S.ed.bits[t][w];
            #pragma unroll 1
            for (int k = 0; k < 16; k++) {
                int c  = tile * 16 + k;
                int wc = c >> 5, kk = c & 31;
                int dl = 512, dr = 512;
                unsigned v = zeros[wc] & (0xffffffffu >> (31 - kk));   // bits <= kk
                int ww = wc;
                while (true) {
                    if (v) { dl = c - (ww * 32 + (31 - __clz(v))); break; }
                    if (--ww < 0) break;
                    v = zeros[ww];
                }
                v = zeros[wc] & (0xffffffffu << kk);                   // bits >= kk
                ww = wc;
                while (true) {
                    if (v) { dr = (ww * 32 + (__ffs(v) - 1)) - c; break; }
                    if (++ww >= NW) break;
                    v = zeros[ww];
                }
                int g = min(min(dl, dr), 512);
                S.ed.shg[k][t] = (float)(g * g);
            }
        }
        __syncthreads();

        // vertical lower envelope (exact early-exit expanding search)
        int c16   = t & 15;
        int ybase = (t >> 4) * 16;
        int gc    = tile * 16 + c16;
        const float* colp = &S.ed.shg[c16][0];
        #pragma unroll 1
        for (int k = 0; k < 16; k++) {
            int y = ybase + k;
            float m = colp[y];
            for (int dy = 1; dy < H; dy++) {
                float d2 = (float)(dy * dy);
                if (d2 >= m) break;
                int ya = y - dy; if (ya >= 0) m = fminf(m, colp[ya] + d2);
                int yb = y + dy; if (yb < H)  m = fminf(m, colp[yb] + d2);
            }
            unsigned mb = (S.ed.bits[y][gc >> 5] >> (gc & 31)) & 1u;
            float dm = mb ? sqrtf(m) : 0.0f;
            S.ed.sdist[c16][y] = dm;
            g_dist[img][y][gc] = dm;                      // coalesced store
        }

        // wait for this image's skeleton, then rmax/rmin from shared
        if (t == 0) {
            while (atomicAdd(&g_flag[img], 0) == 0) { }
            __threadfence();
        }
        __syncthreads();
        S.ed.skelw[t] = g_skelb[img][t][tile >> 1];       // word holding this tile
        __syncthreads();

        float mx = 0.0f, mn = __int_as_float(0x7f7fffff);
        #pragma unroll 1
        for (int k = 0; k < 16; k++) {
            int y = ybase + k;
            unsigned sb = (S.ed.skelw[y] >> (gc & 31)) & 1u;
            float sr = sb ? S.ed.sdist[c16][y] : 0.0f;
            mx = fmaxf(mx, sr);
            mn = fminf(mn, sr);
        }
        #pragma unroll
        for (int o = 16; o; o >>= 1) {
            mx = fmaxf(mx, __shfl_xor_sync(0xffffffffu, mx, o));
            mn = fminf(mn, __shfl_xor_sync(0xffffffffu, mn, o));
        }
        if ((t & 31) == 0) { s_red[0][t >> 5] = mx; s_red[1][t >> 5] = mn; }
        __syncthreads();
        if (t == 0) {
            float a = s_red[0][0], q = s_red[1][0];
            #pragma unroll
            for (int w = 1; w < 8; w++) { a = fmaxf(a, s_red[0][w]); q = fminf(q, s_red[1][w]); }
            atomicMax(&g_rmax[img], __float_as_uint(a));
            atomicMin(&g_rmin[img], __float_as_uint(q));
        }
    }
    grid_bar(2 * NB);

    // ================= Phase C: q-maps + sums + epilogue =================
    if (t < NIMG) {
        s_rmx[t] = fmaxf(__uint_as_float(atomicAdd(&g_rmax[t], 0u)), 1.0f);
        s_rmn[t] = fmaxf(__uint_as_float(atomicAdd(&g_rmin[t], 0u)), 1.0f);
    }
    __syncthreads();

    float t1 = 0.f, d1 = 0.f, t2 = 0.f, d2s = 0.f;
    for (int q = gtid; q < NPIX / 4; q += NTHREADS) {
        int b   = q >> 14;
        int row = (q >> 6) & 255;
        int col = (q & 63) << 2;
        float rmaxL = s_rmx[b * 2 + 0], rminL = s_rmn[b * 2 + 0];
        float rmaxP = s_rmx[b * 2 + 1], rminP = s_rmn[b * 2 + 1];
        float irL = __fdividef(1.0f, rmaxL), irP = __fdividef(1.0f, rmaxP);

        float4 dl4 = __ldcg((const float4*)&g_dist[b * 2 + 0][row][col]);
        float4 dp4 = __ldcg((const float4*)&g_dist[b * 2 + 1][row][col]);
        float4 pp4 = *(const float4*)&g_pp[q * 4];
        int wsh = col & 31, wi = col >> 5;
        unsigned mLw = g_maskb[b * 2 + 0][row][wi] >> wsh;
        unsigned sLw = g_skelb[b * 2 + 0][row][wi] >> wsh;
        unsigned mPw = g_maskb[b * 2 + 1][row][wi] >> wsh;
        unsigned sPw = g_skelb[b * 2 + 1][row][wi] >> wsh;

        float dls[4] = {dl4.x, dl4.y, dl4.z, dl4.w};
        float dps[4] = {dp4.x, dp4.y, dp4.z, dp4.w};
        float pps[4] = {pp4.x, pp4.y, pp4.z, pp4.w};
        #pragma unroll
        for (int j = 0; j < 4; j++) {
            bool mL = (mLw >> j) & 1, sL = (sLw >> j) & 1;
            bool mP = (mPw >> j) & 1, sP = (sPw >> j) & 1;
            float dl = dls[j], dp = dps[j], pp = pps[j];
            float q_vl   = mL ? fminf(dl, rmaxL) * irL : 0.f;
            float q_slvl = sL ? dl * irL : 0.f;
            float q_sl   = sL ? (rmaxL - dl + rminL) * irL : 0.f;
            float q_vp   = mP ? fminf(dp, rmaxP) * irP * pp : 0.f;
            float q_spvp = sP ? dp * irP * pp : 0.f;
            float q_sp   = sP ? (rmaxP - dp + rminP) * irP * pp : 0.f;
            t1  += q_sp * q_vl;
            d1  += (sP && !sL) ? q_spvp * q_sp : q_slvl * q_sp;   // combine_tensors
            t2  += q_sl * q_vp;
            d2s += (sL && !sP) ? q_slvl * q_sl : q_spvp * q_sl;
        }
    }

    #pragma unroll
    for (int o = 16; o; o >>= 1) {
        t1  += __shfl_xor_sync(0xffffffffu, t1,  o);
        d1  += __shfl_xor_sync(0xffffffffu, d1,  o);
        t2  += __shfl_xor_sync(0xffffffffu, t2,  o);
        d2s += __shfl_xor_sync(0xffffffffu, d2s, o);
    }
    if ((t & 31) == 0) { int w = t >> 5; s_w[w][0] = t1; s_w[w][1] = d1; s_w[w][2] = t2; s_w[w][3] = d2s; }
    __syncthreads();

    if (t == 0) {
        double a0 = 0.0, a1 = 0.0, a2 = 0.0, a3 = 0.0;
        #pragma unroll
        for (int w = 0; w < 8; w++) {
            a0 += (double)s_w[w][0]; a1 += (double)s_w[w][1];
            a2 += (double)s_w[w][2]; a3 += (double)s_w[w][3];
        }
        atomicAdd(&g_sums[0], a0);
        atomicAdd(&g_sums[1], a1);
        atomicAdd(&g_sums[2], a2);
        atomicAdd(&g_sums[3], a3);
        __threadfence();
        unsigned done = atomicAdd(&g_count, 1u);
        if (done == NB - 1) {                              // last block: epilogue + reset
            double S1 = atomicAdd(&g_sums[0], 0.0);
            double D1 = atomicAdd(&g_sums[1], 0.0);
            double S2 = atomicAdd(&g_sums[2], 0.0);
            double D2 = atomicAdd(&g_sums[3], 0.0);
            double wp = (S1 + 1.0) / (D1 + 1.0);
            double ws = (S2 + 1.0) / (D2 + 1.0);
            out[0] = (float)(1.0 - 2.0 * (wp * ws) / (wp + ws));
            // reset state for next (graph-replayed) run
            g_bar = 0u; g_count = 0u;
            #pragma unroll
            for (int i = 0; i < NIMG; i++) {
                g_flag[i] = 0; g_rmax[i] = 0u; g_rmin[i] = 0x7f7fffffu;
            }
            #pragma unroll
            for (int i = 0; i < 4; i++) g_sums[i] = 0.0;
            __threadfence();
        }
    }
}

// ---------------- launch ----------------
extern "C" void kernel_launch(void* const* d_in, const int* in_sizes, int n_in,
                              void* d_out, int out_size) {
    const float* ypred = (const float*)d_in[0];
    const int*   ytrue = (const int*)d_in[1];
    float*       out   = (float*)d_out;
    k_fused<<<NB, NT>>>(ypred, ytrue, out);
}

// round 4
// speedup vs baseline: 1.5548x; 1.5548x over previous
#include <cuda_runtime.h>
#include <math.h>

#define H 256
#define W 256
#define NIMG 8              // 4 batches x {true, pred}
#define NW 8                // 256 bits per row
#define NPIX (4*H*W)        // 262144
#define NEDT 128            // 4 batches x 32 tiles (8 cols each)
#define NT 256

// ---------------- device state ----------------
__device__ float    g_pp[NPIX];
__device__ unsigned g_maskb[NIMG][H][NW];
__device__ unsigned g_skelb[NIMG][H][NW];
__device__ unsigned g_rmax[NIMG];
__device__ unsigned g_rmin[NIMG];
__device__ double   g_sums[4];
__device__ int      g_flag[NIMG];
__device__ unsigned g_ebar;
__device__ unsigned g_count;

// ---------------- K1: elementwise (x4 vectorized) + bit packing + resets ----
__global__ void __launch_bounds__(NT) k_prep(const float* __restrict__ ypred,
                                             const int*   __restrict__ ytrue) {
    int gtid = blockIdx.x * NT + threadIdx.x;     // one thread = 4 pixels
    if (blockIdx.x == 0) {
        int t = threadIdx.x;
        if (t < NIMG) { g_rmax[t] = 0u; g_rmin[t] = 0x7f7fffffu; g_flag[t] = 0; }
        if (t < 4)    g_sums[t] = 0.0;
        if (t == 0)   { g_ebar = 0u; g_count = 0u; }
    }
    int base = gtid * 4;
    float4 x4 = *(const float4*)&ypred[base];
    int4   y4 = *(const int4*)&ytrue[base];

    float xs[4] = {x4.x, x4.y, x4.z, x4.w};
    float pps[4];
    #pragma unroll
    for (int j = 0; j < 4; j++) {
        float p  = __fdividef(1.0f, 1.0f + __expf(-xs[j]));
        pps[j]   = __fdividef(1.0f, 1.0f + __expf(1.0f - 2.0f * p));
    }
    *(float4*)&g_pp[base] = make_float4(pps[0], pps[1], pps[2], pps[3]);

    unsigned nibP = (xs[0] > 0.f) | ((xs[1] > 0.f) << 1) | ((xs[2] > 0.f) << 2) | ((xs[3] > 0.f) << 3);
    unsigned nibT = (y4.x > 0) | ((y4.y > 0) << 1) | ((y4.z > 0) << 2) | ((y4.w > 0) << 3);
    int lane = threadIdx.x & 31;
    unsigned sh = (lane & 7) * 4;
    unsigned wP = nibP << sh, wT = nibT << sh;
    #pragma unroll
    for (int o = 1; o < 8; o <<= 1) {
        wP |= __shfl_xor_sync(0xffffffffu, wP, o);
        wT |= __shfl_xor_sync(0xffffffffu, wT, o);
    }
    if ((lane & 7) == 0) {
        int b = base >> 16, row = (base >> 8) & 255, word = (base & 255) >> 5;
        g_maskb[b * 2 + 0][row][word] = wT;
        g_maskb[b * 2 + 1][row][word] = wP;
    }
}

// ---------------- K2: skeleton | fused EDT+minmax+sums ----------------
// blocks [0,8): bitboard skeleton (one per image)
// blocks [8,136): one per (batch, 8-col tile): both images' EDT + q-sums
__global__ void __launch_bounds__(NT) k_all(float* __restrict__ out) {
    __shared__ union Sh {
        struct { unsigned simg[H][NW]; unsigned shd[H][NW]; } sk;           // 16KB
        struct {
            unsigned bits[2][H][NW];     // 16KB  both images' masks
            float    shg[8][257];        // 8.2KB g^2 scratch (per image, reused)
            float    sdist[2][8][257];   // 16.4KB masked distances, tile cols
            unsigned skelw[2][H];        // 2KB   skeleton words for tile
        } ed;                                                                // ~43KB
    } S;
    __shared__ float s_red[4][8];
    __shared__ float s_rr[4];            // rmaxL, rminL, rmaxP, rminP

    const int t = threadIdx.x;

    if (blockIdx.x < NIMG) {
        // ================= skeleton =================
        int img = blockIdx.x;
        unsigned skel[NW];
        #pragma unroll
        for (int w = 0; w < NW; w++) { S.sk.simg[t][w] = g_maskb[img][t][w]; skel[w] = 0u; }
        __syncthreads();
        for (int it = 0; it < 11; it++) {
            unsigned x[NW], e[NW], vu[NW], vd[NW];
            #pragma unroll
            for (int w = 0; w < NW; w++) x[w] = S.sk.simg[t][w];
            #pragma unroll
            for (int w = 0; w < NW; w++) {
                vu[w] = (t > 0)     ? S.sk.simg[t - 1][w] : 0xffffffffu;
                vd[w] = (t < H - 1) ? S.sk.simg[t + 1][w] : 0xffffffffu;
            }
            #pragma unroll
            for (int w = 0; w < NW; w++) {
                unsigned sl = (x[w] << 1) | ((w > 0)      ? (x[w - 1] >> 31) : 1u);
                unsigned sr = (x[w] >> 1) | ((w < NW - 1) ? (x[w + 1] << 31) : 0x80000000u);
                e[w] = vu[w] & vd[w] & x[w] & sl & sr;
            }
            #pragma unroll
            for (int w = 0; w < NW; w++) {
                unsigned ol  = (e[w] << 1) | ((w > 0)      ? (e[w - 1] >> 31) : 0u);
                unsigned orr = (e[w] >> 1) | ((w < NW - 1) ? (e[w + 1] << 31) : 0u);
                S.sk.shd[t][w] = e[w] | ol | orr;
            }
            __syncthreads();
            #pragma unroll
            for (int w = 0; w < NW; w++) {
                unsigned o = S.sk.shd[t][w];
                if (t > 0)     o |= S.sk.shd[t - 1][w];
                if (t < H - 1) o |= S.sk.shd[t + 1][w];
                skel[w] |= x[w] & ~o;
                S.sk.simg[t][w] = e[w];
            }
            __syncthreads();
        }
        #pragma unroll
        for (int w = 0; w < NW; w++) g_skelb[img][t][w] = skel[w];
        __threadfence();
        __syncthreads();
        if (t == 0) atomicExch(&g_flag[img], 1);
        return;
    }

    // ================= EDT + sums: one block per (batch, 8-col tile) ======
    const int bb   = blockIdx.x - NIMG;
    const int bat  = bb >> 5;
    const int tile = bb & 31;
    const int c0   = tile * 8;
    const int wc0  = c0 >> 5;                      // word holding this tile
    const int imgL = bat * 2, imgP = bat * 2 + 1;

    {   // load both bitboards (coalesced)
        unsigned* dst = &S.ed.bits[0][0][0];
        const unsigned* srcL = &g_maskb[imgL][0][0];
        for (int j = t; j < H * NW; j += NT) {
            dst[j]           = srcL[j];
            dst[H * NW + j]  = srcL[H * NW + j];   // imgP is contiguous after imgL
        }
    }
    __syncthreads();

    const int c8    = t & 7;
    const int ybase = (t >> 3) * 8;
    const int gc    = c0 + c8;
    const unsigned shbit = gc & 31;

    #pragma unroll 1
    for (int im = 0; im < 2; im++) {
        // ---- horizontal EDT via bit scans: thread = row ----
        {
            unsigned zeros[NW];
            #pragma unroll
            for (int w = 0; w < NW; w++) zeros[w] = ~S.ed.bits[im][t][w];
            #pragma unroll 1
            for (int k = 0; k < 8; k++) {
                int c = c0 + k;
                int kk = c & 31;
                int dl = 512, dr = 512;
                unsigned v = zeros[wc0] & (0xffffffffu >> (31 - kk));
                int ww = wc0;
                while (true) {
                    if (v) { dl = c - (ww * 32 + (31 - __clz(v))); break; }
                    if (--ww < 0) break;
                    v = zeros[ww];
                }
                v = zeros[wc0] & (0xffffffffu << kk);
                ww = wc0;
                while (true) {
                    if (v) { dr = (ww * 32 + (__ffs(v) - 1)) - c; break; }
                    if (++ww >= NW) break;
                    v = zeros[ww];
                }
                int g = min(min(dl, dr), 512);
                S.ed.shg[k][t] = (float)(g * g);
            }
        }
        __syncthreads();
        // ---- vertical envelope (exact early-exit) ----
        const float* colp = &S.ed.shg[c8][0];
        #pragma unroll 1
        for (int k = 0; k < 8; k++) {
            int y = ybase + k;
            float m = colp[y];
            for (int dy = 1; dy < H; dy++) {
                float d2 = (float)(dy * dy);
                if (d2 >= m) break;
                int ya = y - dy; if (ya >= 0) m = fminf(m, colp[ya] + d2);
                int yb = y + dy; if (yb < H)  m = fminf(m, colp[yb] + d2);
            }
            unsigned mb = (S.ed.bits[im][y][wc0] >> shbit) & 1u;
            S.ed.sdist[im][c8][y] = mb ? sqrtf(m) : 0.0f;
        }
        __syncthreads();
    }

    // ---- wait for both skeletons, fetch tile skeleton words ----
    if (t == 0) {
        while (atomicAdd(&g_flag[imgL], 0) == 0) { }
        while (atomicAdd(&g_flag[imgP], 0) == 0) { }
        __threadfence();
    }
    __syncthreads();
    S.ed.skelw[0][t] = g_skelb[imgL][t][wc0];
    S.ed.skelw[1][t] = g_skelb[imgP][t][wc0];
    __syncthreads();

    // ---- tile rmax/rmin for both images ----
    {
        float mxL = 0.f, mnL = __int_as_float(0x7f7fffff);
        float mxP = 0.f, mnP = __int_as_float(0x7f7fffff);
        #pragma unroll 1
        for (int k = 0; k < 8; k++) {
            int y = ybase + k;
            float srL = ((S.ed.skelw[0][y] >> shbit) & 1u) ? S.ed.sdist[0][c8][y] : 0.f;
            float srP = ((S.ed.skelw[1][y] >> shbit) & 1u) ? S.ed.sdist[1][c8][y] : 0.f;
            mxL = fmaxf(mxL, srL); mnL = fminf(mnL, srL);
            mxP = fmaxf(mxP, srP); mnP = fminf(mnP, srP);
        }
        #pragma unroll
        for (int o = 16; o; o >>= 1) {
            mxL = fmaxf(mxL, __shfl_xor_sync(0xffffffffu, mxL, o));
            mnL = fminf(mnL, __shfl_xor_sync(0xffffffffu, mnL, o));
            mxP = fmaxf(mxP, __shfl_xor_sync(0xffffffffu, mxP, o));
            mnP = fminf(mnP, __shfl_xor_sync(0xffffffffu, mnP, o));
        }
        if ((t & 31) == 0) {
            int w = t >> 5;
            s_red[0][w] = mxL; s_red[1][w] = mnL; s_red[2][w] = mxP; s_red[3][w] = mnP;
        }
        __syncthreads();
        if (t == 0) {
            float a = s_red[0][0], b = s_red[1][0], c = s_red[2][0], d = s_red[3][0];
            #pragma unroll
            for (int w = 1; w < 8; w++) {
                a = fmaxf(a, s_red[0][w]); b = fminf(b, s_red[1][w]);
                c = fmaxf(c, s_red[2][w]); d = fminf(d, s_red[3][w]);
            }
            atomicMax(&g_rmax[imgL], __float_as_uint(a));
            atomicMin(&g_rmin[imgL], __float_as_uint(b));
            atomicMax(&g_rmax[imgP], __float_as_uint(c));
            atomicMin(&g_rmin[imgP], __float_as_uint(d));
            __threadfence();
            atomicAdd(&g_ebar, 1u);                 // join EDT barrier
            while (atomicAdd(&g_ebar, 0u) < NEDT) { }
            __threadfence();
            s_rr[0] = fmaxf(__uint_as_float(atomicAdd(&g_rmax[imgL], 0u)), 1.0f);
            s_rr[1] = fmaxf(__uint_as_float(atomicAdd(&g_rmin[imgL], 0u)), 1.0f);
            s_rr[2] = fmaxf(__uint_as_float(atomicAdd(&g_rmax[imgP], 0u)), 1.0f);
            s_rr[3] = fmaxf(__uint_as_float(atomicAdd(&g_rmin[imgP], 0u)), 1.0f);
        }
        __syncthreads();
    }
    const float rmaxL = s_rr[0], rminL = s_rr[1], rmaxP = s_rr[2], rminP = s_rr[3];
    const float irL = __fdividef(1.0f, rmaxL), irP = __fdividef(1.0f, rmaxP);

    // ---- q-maps + partial sums (all data in shared except pp) ----
    float t1 = 0.f, d1 = 0.f, t2 = 0.f, d2s = 0.f;
    #pragma unroll 1
    for (int k = 0; k < 8; k++) {
        int y = ybase + k;
        bool mL = (S.ed.bits[0][y][wc0] >> shbit) & 1u;
        bool mP = (S.ed.bits[1][y][wc0] >> shbit) & 1u;
        bool sL = (S.ed.skelw[0][y] >> shbit) & 1u;
        bool sP = (S.ed.skelw[1][y] >> shbit) & 1u;
        float dl = S.ed.sdist[0][c8][y];
        float dp = S.ed.sdist[1][c8][y];
        float pp = g_pp[bat * 65536 + y * 256 + gc];

        float q_vl   = mL ? fminf(dl, rmaxL) * irL : 0.f;
        float q_slvl = sL ? dl * irL : 0.f;
        float q_sl   = sL ? (rmaxL - dl + rminL) * irL : 0.f;
        float q_vp   = mP ? fminf(dp, rmaxP) * irP * pp : 0.f;
        float q_spvp = sP ? dp * irP * pp : 0.f;
        float q_sp   = sP ? (rmaxP - dp + rminP) * irP * pp : 0.f;
        t1  += q_sp * q_vl;
        d1  += (sP && !sL) ? q_spvp * q_sp : q_slvl * q_sp;     // combine_tensors
        t2  += q_sl * q_vp;
        d2s += (sL && !sP) ? q_slvl * q_sl : q_spvp * q_sl;
    }
    #pragma unroll
    for (int o = 16; o; o >>= 1) {
        t1  += __shfl_xor_sync(0xffffffffu, t1,  o);
        d1  += __shfl_xor_sync(0xffffffffu, d1,  o);
        t2  += __shfl_xor_sync(0xffffffffu, t2,  o);
        d2s += __shfl_xor_sync(0xffffffffu, d2s, o);
    }
    if ((t & 31) == 0) {
        int w = t >> 5;
        s_red[0][w] = t1; s_red[1][w] = d1; s_red[2][w] = t2; s_red[3][w] = d2s;
    }
    __syncthreads();
    if (t == 0) {
        double a0 = 0.0, a1 = 0.0, a2 = 0.0, a3 = 0.0;
        #pragma unroll
        for (int w = 0; w < 8; w++) {
            a0 += (double)s_red[0][w]; a1 += (double)s_red[1][w];
            a2 += (double)s_red[2][w]; a3 += (double)s_red[3][w];
        }
        atomicAdd(&g_sums[0], a0);
        atomicAdd(&g_sums[1], a1);
        atomicAdd(&g_sums[2], a2);
        atomicAdd(&g_sums[3], a3);
        __threadfence();
        unsigned done = atomicAdd(&g_count, 1u);
        if (done == NEDT - 1) {
            double S1 = atomicAdd(&g_sums[0], 0.0);
            double D1 = atomicAdd(&g_sums[1], 0.0);
            double S2 = atomicAdd(&g_sums[2], 0.0);
            double D2 = atomicAdd(&g_sums[3], 0.0);
            double wp = (S1 + 1.0) / (D1 + 1.0);
            double ws = (S2 + 1.0) / (D2 + 1.0);
            out[0] = (float)(1.0 - 2.0 * (wp * ws) / (wp + ws));
        }
    }
}

// ---------------- launch ----------------
extern "C" void kernel_launch(void* const* d_in, const int* in_sizes, int n_in,
                              void* d_out, int out_size) {
    const float* ypred = (const float*)d_in[0];
    const int*   ytrue = (const int*)d_in[1];
    float*       out   = (float*)d_out;
    k_prep<<<NPIX / (NT * 4), NT>>>(ypred, ytrue);
    k_all <<<NIMG + NEDT, NT>>>(out);
}

// round 5
// speedup vs baseline: 1.8263x; 1.1746x over previous
#include <cuda_runtime.h>
#include <math.h>

#define H 256
#define W 256
#define NIMG 8              // 4 batches x {true, pred}
#define NW 8                // 256 bits per row
#define NPIX (4*H*W)        // 262144
#define NSK 64              // 8 images x 8 row-strips (32 rows + 12 halo)
#define NEDT 128            // 4 batches x 32 col-tiles (8 cols)
#define NT 256

// ---------------- device state ----------------
__device__ float    g_pp[NPIX];
__device__ unsigned g_maskb[NIMG][H][NW];
__device__ unsigned g_skelb[NIMG][H][NW];
__device__ unsigned g_rmax[NIMG];
__device__ unsigned g_rmin[NIMG];
__device__ double   g_sums[4];
__device__ unsigned g_sdone[NIMG];           // strips completed per image
__device__ unsigned g_ebar;
__device__ unsigned g_count;

// ---------------- K1: elementwise (x4) + bit packing + resets ----------------
__global__ void __launch_bounds__(NT) k_prep(const float* __restrict__ ypred,
                                             const int*   __restrict__ ytrue) {
    int gtid = blockIdx.x * NT + threadIdx.x;     // one thread = 4 pixels
    if (blockIdx.x == 0) {
        int t = threadIdx.x;
        if (t < NIMG) { g_rmax[t] = 0u; g_rmin[t] = 0x7f7fffffu; g_sdone[t] = 0u; }
        if (t < 4)    g_sums[t] = 0.0;
        if (t == 0)   { g_ebar = 0u; g_count = 0u; }
    }
    int base = gtid * 4;
    float4 x4 = *(const float4*)&ypred[base];
    int4   y4 = *(const int4*)&ytrue[base];
    float xs[4] = {x4.x, x4.y, x4.z, x4.w};
    float pps[4];
    #pragma unroll
    for (int j = 0; j < 4; j++) {
        float p  = __fdividef(1.0f, 1.0f + __expf(-xs[j]));
        pps[j]   = __fdividef(1.0f, 1.0f + __expf(1.0f - 2.0f * p));
    }
    *(float4*)&g_pp[base] = make_float4(pps[0], pps[1], pps[2], pps[3]);

    unsigned nibP = (xs[0] > 0.f) | ((xs[1] > 0.f) << 1) | ((xs[2] > 0.f) << 2) | ((xs[3] > 0.f) << 3);
    unsigned nibT = (y4.x > 0) | ((y4.y > 0) << 1) | ((y4.z > 0) << 2) | ((y4.w > 0) << 3);
    int lane = threadIdx.x & 31;
    unsigned sh = (lane & 7) * 4;
    unsigned wP = nibP << sh, wT = nibT << sh;
    #pragma unroll
    for (int o = 1; o < 8; o <<= 1) {
        wP |= __shfl_xor_sync(0xffffffffu, wP, o);
        wT |= __shfl_xor_sync(0xffffffffu, wT, o);
    }
    if ((lane & 7) == 0) {
        int b = base >> 16, row = (base >> 8) & 255, word = (base & 255) >> 5;
        g_maskb[b * 2 + 0][row][word] = wT;
        g_maskb[b * 2 + 1][row][word] = wP;
    }
}

// ---------------- K2: parallel-strip skeleton | fused EDT+minmax+sums -------
__global__ void __launch_bounds__(NT) k_all(float* __restrict__ out) {
    __shared__ __align__(16) union Sh {
        struct { unsigned ss[56][NW]; unsigned sd[56][NW]; } sk;        // 3.5KB
        struct {
            unsigned bits[2][H][NW];      // 16KB   both images' masks
            float    shg[2][8][257];      // 16.4KB g^2 per image (tile cols)
            unsigned skelw[2][H];         // 2KB    skeleton words for tile
        } ed;                                                            // ~35KB
    } S;
    __shared__ float s_red[4][8];
    __shared__ float s_rr[4];

    const int t = threadIdx.x;

    if (blockIdx.x < NSK) {
        // ============ skeleton strip: img x 32-row strip with 12-row halo ====
        const int img = blockIdx.x >> 3;
        const int r0  = (blockIdx.x & 7) * 32;
        const int lr  = t;                      // buffer row 0..55
        const bool active = lr < 56;
        const int gr = r0 - 12 + lr;            // global row (may be OOB)
        const bool inimg = (gr >= 0 && gr < H);
        const int lu = lr > 0 ? lr - 1 : 0;
        const int ld = lr < 55 ? lr + 1 : 55;

        unsigned cur[NW], skel[NW];
        if (active) {
            #pragma unroll
            for (int w = 0; w < NW; w++) {
                cur[w] = inimg ? g_maskb[img][gr][w] : 0u;
                S.sk.ss[lr][w] = cur[w];
                skel[w] = 0u;
            }
        }
        __syncthreads();

        for (int it = 0; it < 11; it++) {
            unsigned e[NW], hd[NW];
            if (active) {
                #pragma unroll
                for (int w = 0; w < NW; w++) {
                    unsigned vu = (gr == 0)     ? 0xffffffffu : S.sk.ss[lu][w];
                    unsigned vd = (gr == H - 1) ? 0xffffffffu : S.sk.ss[ld][w];
                    unsigned x  = cur[w];
                    unsigned sl = (x << 1) | ((w > 0)      ? (cur[w - 1] >> 31) : 1u);
                    unsigned sr = (x >> 1) | ((w < NW - 1) ? (cur[w + 1] << 31) : 0x80000000u);
                    e[w] = vu & vd & x & sl & sr;
                }
                #pragma unroll
                for (int w = 0; w < NW; w++) {
                    unsigned ol  = (e[w] << 1) | ((w > 0)      ? (e[w - 1] >> 31) : 0u);
                    unsigned orr = (e[w] >> 1) | ((w < NW - 1) ? (e[w + 1] << 31) : 0u);
                    hd[w] = e[w] | ol | orr;
                }
            }
            __syncthreads();                    // all reads of old ss done
            if (active) {
                #pragma unroll
                for (int w = 0; w < NW; w++) { S.sk.ss[lr][w] = e[w]; S.sk.sd[lr][w] = hd[w]; }
            }
            __syncthreads();
            if (active) {
                #pragma unroll
                for (int w = 0; w < NW; w++) {
                    unsigned o = hd[w];
                    if (gr != 0)     o |= S.sk.sd[lu][w];
                    if (gr != H - 1) o |= S.sk.sd[ld][w];
                    skel[w] |= cur[w] & ~o;
                    cur[w] = e[w];
                }
            }
        }
        if (active && gr >= r0 && gr < r0 + 32) {
            #pragma unroll
            for (int w = 0; w < NW; w++) g_skelb[img][gr][w] = skel[w];
        }
        __threadfence();
        __syncthreads();
        if (t == 0) atomicAdd(&g_sdone[img], 1u);
        return;
    }

    // ============ EDT + sums: one block per (batch, 8-col tile) =============
    const int bb   = blockIdx.x - NSK;
    const int bat  = bb >> 5;
    const int tile = bb & 31;
    const int c0   = tile * 8;
    const int wc0  = c0 >> 5;
    const int imgL = bat * 2, imgP = bat * 2 + 1;

    {   // load both bitboards (vectorized, imgP contiguous after imgL)
        uint4* dst = (uint4*)&S.ed.bits[0][0][0];
        const uint4* src = (const uint4*)&g_maskb[imgL][0][0];
        #pragma unroll
        for (int j = 0; j < 4; j++) dst[t + j * NT] = src[t + j * NT];
    }
    __syncthreads();

    // ---- horizontal EDT via bit scans (both images interleaved), thread=row
    #pragma unroll 1
    for (int k = 0; k < 8; k++) {
        int c = c0 + k, kk = c & 31;
        unsigned mLo = 0xffffffffu >> (31 - kk);
        unsigned mHi = 0xffffffffu << kk;
        int dl0 = 512, dr0 = 512, dl1 = 512, dr1 = 512;
        {
            unsigned v0 = ~S.ed.bits[0][t][wc0] & mLo;
            unsigned v1 = ~S.ed.bits[1][t][wc0] & mLo;
            int w0 = wc0, w1 = wc0;
            while (true) { if (v0) { dl0 = c - (w0 * 32 + 31 - __clz(v0)); break; }
                           if (--w0 < 0) break; v0 = ~S.ed.bits[0][t][w0]; }
            while (true) { if (v1) { dl1 = c - (w1 * 32 + 31 - __clz(v1)); break; }
                           if (--w1 < 0) break; v1 = ~S.ed.bits[1][t][w1]; }
        }
        {
            unsigned v0 = ~S.ed.bits[0][t][wc0] & mHi;
            unsigned v1 = ~S.ed.bits[1][t][wc0] & mHi;
            int w0 = wc0, w1 = wc0;
            while (true) { if (v0) { dr0 = (w0 * 32 + __ffs(v0) - 1) - c; break; }
                           if (++w0 >= NW) break; v0 = ~S.ed.bits[0][t][w0]; }
            while (true) { if (v1) { dr1 = (w1 * 32 + __ffs(v1) - 1) - c; break; }
                           if (++w1 >= NW) break; v1 = ~S.ed.bits[1][t][w1]; }
        }
        int g0 = min(min(dl0, dr0), 512), g1 = min(min(dl1, dr1), 512);
        S.ed.shg[0][k][t] = (float)(g0 * g0);
        S.ed.shg[1][k][t] = (float)(g1 * g1);
    }
    __syncthreads();

    // ---- vertical envelope: speculative unroll-by-4, both images ----
    const int c8    = t & 7;
    const int ybase = (t >> 3) * 8;
    const int gc    = c0 + c8;
    const unsigned shbit = gc & 31;
    const float* cp0 = &S.ed.shg[0][c8][0];
    const float* cp1 = &S.ed.shg[1][c8][0];
    float dm0[8], dm1[8];
    #pragma unroll 1
    for (int k = 0; k < 8; k++) {
        int y = ybase + k;
        float m0 = cp0[y], m1 = cp1[y];
        int dy = 1;
        while ((float)(dy * dy) < fmaxf(m0, m1) && dy < H) {
            #pragma unroll
            for (int j = 0; j < 4; j++) {       // clamped candidates: safe overestimates
                int d = dy + j;
                float d2 = (float)(d * d);
                int ya = y - d; ya = ya < 0 ? 0 : ya;
                int yb = y + d; yb = yb > H - 1 ? H - 1 : yb;
                m0 = fminf(m0, fminf(cp0[ya], cp0[yb]) + d2);
                m1 = fminf(m1, fminf(cp1[ya], cp1[yb]) + d2);
            }
            dy += 4;
        }
        unsigned mb0 = (S.ed.bits[0][y][wc0] >> shbit) & 1u;
        unsigned mb1 = (S.ed.bits[1][y][wc0] >> shbit) & 1u;
        dm0[k] = mb0 ? sqrtf(m0) : 0.0f;
        dm1[k] = mb1 ? sqrtf(m1) : 0.0f;
    }

    // ---- wait for both images' skeletons (volatile poll, no RMW) ----
    if (t == 0) {
        volatile unsigned* sL = &g_sdone[imgL];
        volatile unsigned* sP = &g_sdone[imgP];
        while (*sL < 8u || *sP < 8u) __nanosleep(64);
        __threadfence();
    }
    __syncthreads();
    S.ed.skelw[0][t] = g_skelb[imgL][t][wc0];
    S.ed.skelw[1][t] = g_skelb[imgP][t][wc0];
    __syncthreads();

    // ---- tile rmax/rmin for both images ----
    {
        float mxL = 0.f, mnL = __int_as_float(0x7f7fffff);
        float mxP = 0.f, mnP = __int_as_float(0x7f7fffff);
        #pragma unroll
        for (int k = 0; k < 8; k++) {
            int y = ybase + k;
            float srL = ((S.ed.skelw[0][y] >> shbit) & 1u) ? dm0[k] : 0.f;
            float srP = ((S.ed.skelw[1][y] >> shbit) & 1u) ? dm1[k] : 0.f;
            mxL = fmaxf(mxL, srL); mnL = fminf(mnL, srL);
            mxP = fmaxf(mxP, srP); mnP = fminf(mnP, srP);
        }
        #pragma unroll
        for (int o = 16; o; o >>= 1) {
            mxL = fmaxf(mxL, __shfl_xor_sync(0xffffffffu, mxL, o));
            mnL = fminf(mnL, __shfl_xor_sync(0xffffffffu, mnL, o));
            mxP = fmaxf(mxP, __shfl_xor_sync(0xffffffffu, mxP, o));
            mnP = fminf(mnP, __shfl_xor_sync(0xffffffffu, mnP, o));
        }
        if ((t & 31) == 0) {
            int w = t >> 5;
            s_red[0][w] = mxL; s_red[1][w] = mnL; s_red[2][w] = mxP; s_red[3][w] = mnP;
        }
        __syncthreads();
        if (t == 0) {
            float a = s_red[0][0], b = s_red[1][0], c = s_red[2][0], d = s_red[3][0];
            #pragma unroll
            for (int w = 1; w < 8; w++) {
                a = fmaxf(a, s_red[0][w]); b = fminf(b, s_red[1][w]);
                c = fmaxf(c, s_red[2][w]); d = fminf(d, s_red[3][w]);
            }
            atomicMax(&g_rmax[imgL], __float_as_uint(a));
            atomicMin(&g_rmin[imgL], __float_as_uint(b));
            atomicMax(&g_rmax[imgP], __float_as_uint(c));
            atomicMin(&g_rmin[imgP], __float_as_uint(d));
            __threadfence();
            atomicAdd(&g_ebar, 1u);
            volatile unsigned* eb = &g_ebar;
            while (*eb < NEDT) __nanosleep(64);
            __threadfence();
            s_rr[0] = fmaxf(__uint_as_float(*(volatile unsigned*)&g_rmax[imgL]), 1.0f);
            s_rr[1] = fmaxf(__uint_as_float(*(volatile unsigned*)&g_rmin[imgL]), 1.0f);
            s_rr[2] = fmaxf(__uint_as_float(*(volatile unsigned*)&g_rmax[imgP]), 1.0f);
            s_rr[3] = fmaxf(__uint_as_float(*(volatile unsigned*)&g_rmin[imgP]), 1.0f);
        }
        __syncthreads();
    }
    const float rmaxL = s_rr[0], rminL = s_rr[1], rmaxP = s_rr[2], rminP = s_rr[3];
    const float irL = __fdividef(1.0f, rmaxL), irP = __fdividef(1.0f, rmaxP);

    // ---- q-maps + partial sums (register data; only pp from global) ----
    float t1 = 0.f, d1 = 0.f, t2 = 0.f, d2s = 0.f;
    #pragma unroll
    for (int k = 0; k < 8; k++) {
        int y = ybase + k;
        bool mL = (S.ed.bits[0][y][wc0] >> shbit) & 1u;
        bool mP = (S.ed.bits[1][y][wc0] >> shbit) & 1u;
        bool sL = (S.ed.skelw[0][y] >> shbit) & 1u;
        bool sP = (S.ed.skelw[1][y] >> shbit) & 1u;
        float dl = dm0[k], dp = dm1[k];
        float pp = g_pp[bat * 65536 + y * 256 + gc];

        float q_vl   = mL ? fminf(dl, rmaxL) * irL : 0.f;
        float q_slvl = sL ? dl * irL : 0.f;
        float q_sl   = sL ? (rmaxL - dl + rminL) * irL : 0.f;
        float q_vp   = mP ? fminf(dp, rmaxP) * irP * pp : 0.f;
        float q_spvp = sP ? dp * irP * pp : 0.f;
        float q_sp   = sP ? (rmaxP - dp + rminP) * irP * pp : 0.f;
        t1  += q_sp * q_vl;
        d1  += (sP && !sL) ? q_spvp * q_sp : q_slvl * q_sp;   // combine_tensors
        t2  += q_sl * q_vp;
        d2s += (sL && !sP) ? q_slvl * q_sl : q_spvp * q_sl;
    }
    #pragma unroll
    for (int o = 16; o; o >>= 1) {
        t1  += __shfl_xor_sync(0xffffffffu, t1,  o);
        d1  += __shfl_xor_sync(0xffffffffu, d1,  o);
        t2  += __shfl_xor_sync(0xffffffffu, t2,  o);
        d2s += __shfl_xor_sync(0xffffffffu, d2s, o);
    }
    if ((t & 31) == 0) {
        int w = t >> 5;
        s_red[0][w] = t1; s_red[1][w] = d1; s_red[2][w] = t2; s_red[3][w] = d2s;
    }
    __syncthreads();
    if (t == 0) {
        double a0 = 0.0, a1 = 0.0, a2 = 0.0, a3 = 0.0;
        #pragma unroll
        for (int w = 0; w < 8; w++) {
            a0 += (double)s_red[0][w]; a1 += (double)s_red[1][w];
            a2 += (double)s_red[2][w]; a3 += (double)s_red[3][w];
        }
        atomicAdd(&g_sums[0], a0);
        atomicAdd(&g_sums[1], a1);
        atomicAdd(&g_sums[2], a2);
        atomicAdd(&g_sums[3], a3);
        __threadfence();
        unsigned done = atomicAdd(&g_count, 1u);
        if (done == NEDT - 1) {
            double S1 = atomicAdd(&g_sums[0], 0.0);
            double D1 = atomicAdd(&g_sums[1], 0.0);
            double S2 = atomicAdd(&g_sums[2], 0.0);
            double D2 = atomicAdd(&g_sums[3], 0.0);
            double wp = (S1 + 1.0) / (D1 + 1.0);
            double ws = (S2 + 1.0) / (D2 + 1.0);
            out[0] = (float)(1.0 - 2.0 * (wp * ws) / (wp + ws));
        }
    }
}

// ---------------- launch ----------------
extern "C" void kernel_launch(void* const* d_in, const int* in_sizes, int n_in,
                              void* d_out, int out_size) {
    const float* ypred = (const float*)d_in[0];
    const int*   ytrue = (const int*)d_in[1];
    float*       out   = (float*)d_out;
    k_prep<<<NPIX / (NT * 4), NT>>>(ypred, ytrue);
    k_all <<<NSK + NEDT, NT>>>(out);
}

// round 6
// speedup vs baseline: 2.2597x; 1.2373x over previous
#include <cuda_runtime.h>
#include <math.h>

#define H 256
#define W 256
#define NW 8                 // 256 bits per row
#define NPIX (4*H*W)         // 262144
#define NB 128               // 4 batches x 32 col-tiles; <=148 SMs (co-resident)
#define NT 256

// ---------------- device state (reset by last block's epilogue) ----------------
__device__ float    g_pp[NPIX];
__device__ unsigned g_maskb[8][H][NW];
__device__ unsigned g_rmax[8];
__device__ unsigned g_rmin[8] = {0x7f7fffffu,0x7f7fffffu,0x7f7fffffu,0x7f7fffffu,
                                 0x7f7fffffu,0x7f7fffffu,0x7f7fffffu,0x7f7fffffu};
__device__ double   g_sums[4];
__device__ unsigned g_bar1;          // prep barrier
__device__ unsigned g_ebar;          // rmax/rmin barrier
__device__ unsigned g_count;

__global__ void __launch_bounds__(NT) k_fused(const float* __restrict__ ypred,
                                              const int*   __restrict__ ytrue,
                                              float*       __restrict__ out) {
    __shared__ __align__(16) struct {
        unsigned bits[2][H][NW];                       // 16KB both images' masks
        union {
            struct { unsigned ss[2][H][3]; unsigned sd[2][H][3]; } sk;  // 12.3KB
            float shg[2][8][257];                                       // 16.4KB
        } u;
        unsigned skelw[2][H];                          // 2KB tile-word skeleton
    } S;
    __shared__ float s_red[4][8];
    __shared__ float s_rr[4];

    const int t = threadIdx.x;

    // ================= Phase P: prep (2048 px per block) =================
    #pragma unroll
    for (int j = 0; j < 2; j++) {
        int base = blockIdx.x * 2048 + j * 1024 + t * 4;
        float4 x4 = *(const float4*)&ypred[base];
        int4   y4 = *(const int4*)&ytrue[base];
        float xs[4] = {x4.x, x4.y, x4.z, x4.w};
        float pps[4];
        #pragma unroll
        for (int q = 0; q < 4; q++) {
            float p = __fdividef(1.0f, 1.0f + __expf(-xs[q]));
            pps[q]  = __fdividef(1.0f, 1.0f + __expf(1.0f - 2.0f * p));
        }
        *(float4*)&g_pp[base] = make_float4(pps[0], pps[1], pps[2], pps[3]);

        unsigned nibP = (xs[0] > 0.f) | ((xs[1] > 0.f) << 1) | ((xs[2] > 0.f) << 2) | ((xs[3] > 0.f) << 3);
        unsigned nibT = (y4.x > 0) | ((y4.y > 0) << 1) | ((y4.z > 0) << 2) | ((y4.w > 0) << 3);
        int lane = t & 31;
        unsigned sh = (lane & 7) * 4;
        unsigned wP = nibP << sh, wT = nibT << sh;
        #pragma unroll
        for (int o = 1; o < 8; o <<= 1) {
            wP |= __shfl_xor_sync(0xffffffffu, wP, o);
            wT |= __shfl_xor_sync(0xffffffffu, wT, o);
        }
        if ((lane & 7) == 0) {
            int b = base >> 16, row = (base >> 8) & 255, word = (base & 255) >> 5;
            g_maskb[b * 2 + 0][row][word] = wT;
            g_maskb[b * 2 + 1][row][word] = wP;
        }
    }
    // ---- grid barrier 1 ----
    __syncthreads();
    if (t == 0) {
        __threadfence();
        atomicAdd(&g_bar1, 1u);
        volatile unsigned* vb = &g_bar1;
        while (*vb < NB) __nanosleep(32);
        __threadfence();
    }
    __syncthreads();

    // ================= Phase E: per (batch, 8-col tile) =================
    const int bat  = blockIdx.x >> 5;
    const int tile = blockIdx.x & 31;
    const int c0   = tile * 8;
    const int wc0  = c0 >> 5;
    const int imgL = bat * 2, imgP = bat * 2 + 1;

    {   // load both bitboards (vectorized; imgP contiguous after imgL)
        uint4* dst = (uint4*)&S.bits[0][0][0];
        const uint4* src = (const uint4*)&g_maskb[imgL][0][0];
        #pragma unroll
        for (int j = 0; j < 4; j++) dst[t + j * NT] = src[t + j * NT];
    }
    __syncthreads();

    // ---- band skeleton: 2 words covering tile +/-12 col margin, exact ----
    {
        int wbs = (c0 - 12) < 0 ? 0 : ((c0 - 12) >> 5);
        const int wb = wbs > 6 ? 6 : wbs;
        const int tw = wc0 - wb;                  // tile's word within band (0 or 1)
        unsigned cur[2][2], skel[2][2];
        #pragma unroll
        for (int im = 0; im < 2; im++)
            #pragma unroll
            for (int w = 0; w < 2; w++) {
                cur[im][w] = S.bits[im][t][wb + w];
                S.u.sk.ss[im][t][w] = cur[im][w];
                skel[im][w] = 0u;
            }
        __syncthreads();

        for (int it = 0; it < 11; it++) {
            unsigned e[2][2], hd[2][2];
            #pragma unroll
            for (int im = 0; im < 2; im++) {
                unsigned x0 = cur[im][0], x1 = cur[im][1];
                unsigned vu0 = (t == 0)     ? 0xffffffffu : S.u.sk.ss[im][t - 1][0];
                unsigned vu1 = (t == 0)     ? 0xffffffffu : S.u.sk.ss[im][t - 1][1];
                unsigned vd0 = (t == H - 1) ? 0xffffffffu : S.u.sk.ss[im][t + 1][0];
                unsigned vd1 = (t == H - 1) ? 0xffffffffu : S.u.sk.ss[im][t + 1][1];
                unsigned sl0 = (x0 << 1) | 1u;
                unsigned sl1 = (x1 << 1) | (x0 >> 31);
                unsigned sr0 = (x0 >> 1) | (x1 << 31);
                unsigned sr1 = (x1 >> 1) | 0x80000000u;
                e[im][0] = vu0 & vd0 & x0 & sl0 & sr0;
                e[im][1] = vu1 & vd1 & x1 & sl1 & sr1;
                unsigned e0 = e[im][0], e1 = e[im][1];
                hd[im][0] = e0 | (e0 << 1) | (e0 >> 1) | (e1 << 31);
                hd[im][1] = e1 | (e1 << 1) | (e0 >> 31) | (e1 >> 1);
            }
            __syncthreads();                       // old ss reads done
            #pragma unroll
            for (int im = 0; im < 2; im++)
                #pragma unroll
                for (int w = 0; w < 2; w++) {
                    S.u.sk.ss[im][t][w] = e[im][w];
                    S.u.sk.sd[im][t][w] = hd[im][w];
                }
            __syncthreads();
            #pragma unroll
            for (int im = 0; im < 2; im++)
                #pragma unroll
                for (int w = 0; w < 2; w++) {
                    unsigned o = hd[im][w];
                    if (t > 0)     o |= S.u.sk.sd[im][t - 1][w];
                    if (t < H - 1) o |= S.u.sk.sd[im][t + 1][w];
                    skel[im][w] |= cur[im][w] & ~o;
                    cur[im][w] = e[im][w];
                }
        }
        S.skelw[0][t] = skel[0][tw];
        S.skelw[1][t] = skel[1][tw];
        __syncthreads();                           // skeleton done; shg may overlay
    }

    // ---- horizontal EDT via bit scans (both images), thread = row ----
    #pragma unroll 1
    for (int k = 0; k < 8; k++) {
        int c = c0 + k, kk = c & 31;
        unsigned mLo = 0xffffffffu >> (31 - kk);
        unsigned mHi = 0xffffffffu << kk;
        int dl0 = 512, dr0 = 512, dl1 = 512, dr1 = 512;
        {
            unsigned v0 = ~S.bits[0][t][wc0] & mLo;
            unsigned v1 = ~S.bits[1][t][wc0] & mLo;
            int w0 = wc0, w1 = wc0;
            while (true) { if (v0) { dl0 = c - (w0 * 32 + 31 - __clz(v0)); break; }
                           if (--w0 < 0) break; v0 = ~S.bits[0][t][w0]; }
            while (true) { if (v1) { dl1 = c - (w1 * 32 + 31 - __clz(v1)); break; }
                           if (--w1 < 0) break; v1 = ~S.bits[1][t][w1]; }
        }
        {
            unsigned v0 = ~S.bits[0][t][wc0] & mHi;
            unsigned v1 = ~S.bits[1][t][wc0] & mHi;
            int w0 = wc0, w1 = wc0;
            while (true) { if (v0) { dr0 = (w0 * 32 + __ffs(v0) - 1) - c; break; }
                           if (++w0 >= NW) break; v0 = ~S.bits[0][t][w0]; }
            while (true) { if (v1) { dr1 = (w1 * 32 + __ffs(v1) - 1) - c; break; }
                           if (++w1 >= NW) break; v1 = ~S.bits[1][t][w1]; }
        }
        int g0 = min(min(dl0, dr0), 512), g1 = min(min(dl1, dr1), 512);
        S.u.shg[0][k][t] = (float)(g0 * g0);
        S.u.shg[1][k][t] = (float)(g1 * g1);
    }
    __syncthreads();

    // ---- vertical envelope: speculative unroll-by-4, both images ----
    const int c8    = t & 7;
    const int ybase = (t >> 3) * 8;
    const int gc    = c0 + c8;
    const unsigned shbit = gc & 31;
    const float* cp0 = &S.u.shg[0][c8][0];
    const float* cp1 = &S.u.shg[1][c8][0];
    float dm0[8], dm1[8];
    #pragma unroll 1
    for (int k = 0; k < 8; k++) {
        int y = ybase + k;
        float m0 = cp0[y], m1 = cp1[y];
        int dy = 1;
        while ((float)(dy * dy) < fmaxf(m0, m1) && dy < H) {
            #pragma unroll
            for (int j = 0; j < 4; j++) {          // clamped = safe overestimates
                int d = dy + j;
                float d2 = (float)(d * d);
                int ya = y - d; ya = ya < 0 ? 0 : ya;
                int yb = y + d; yb = yb > H - 1 ? H - 1 : yb;
                m0 = fminf(m0, fminf(cp0[ya], cp0[yb]) + d2);
                m1 = fminf(m1, fminf(cp1[ya], cp1[yb]) + d2);
            }
            dy += 4;
        }
        unsigned mb0 = (S.bits[0][y][wc0] >> shbit) & 1u;
        unsigned mb1 = (S.bits[1][y][wc0] >> shbit) & 1u;
        dm0[k] = mb0 ? sqrtf(m0) : 0.0f;
        dm1[k] = mb1 ? sqrtf(m1) : 0.0f;
    }

    // ---- tile rmax/rmin for both images + global barrier ----
    {
        float mxL = 0.f, mnL = __int_as_float(0x7f7fffff);
        float mxP = 0.f, mnP = __int_as_float(0x7f7fffff);
        #pragma unroll
        for (int k = 0; k < 8; k++) {
            int y = ybase + k;
            float srL = ((S.skelw[0][y] >> shbit) & 1u) ? dm0[k] : 0.f;
            float srP = ((S.skelw[1][y] >> shbit) & 1u) ? dm1[k] : 0.f;
            mxL = fmaxf(mxL, srL); mnL = fminf(mnL, srL);
            mxP = fmaxf(mxP, srP); mnP = fminf(mnP, srP);
        }
        #pragma unroll
        for (int o = 16; o; o >>= 1) {
            mxL = fmaxf(mxL, __shfl_xor_sync(0xffffffffu, mxL, o));
            mnL = fminf(mnL, __shfl_xor_sync(0xffffffffu, mnL, o));
            mxP = fmaxf(mxP, __shfl_xor_sync(0xffffffffu, mxP, o));
            mnP = fminf(mnP, __shfl_xor_sync(0xffffffffu, mnP, o));
        }
        if ((t & 31) == 0) {
            int w = t >> 5;
            s_red[0][w] = mxL; s_red[1][w] = mnL; s_red[2][w] = mxP; s_red[3][w] = mnP;
        }
        __syncthreads();
        if (t == 0) {
            float a = s_red[0][0], b = s_red[1][0], c = s_red[2][0], d = s_red[3][0];
            #pragma unroll
            for (int w = 1; w < 8; w++) {
                a = fmaxf(a, s_red[0][w]); b = fminf(b, s_red[1][w]);
                c = fmaxf(c, s_red[2][w]); d = fminf(d, s_red[3][w]);
            }
            atomicMax(&g_rmax[imgL], __float_as_uint(a));
            atomicMin(&g_rmin[imgL], __float_as_uint(b));
            atomicMax(&g_rmax[imgP], __float_as_uint(c));
            atomicMin(&g_rmin[imgP], __float_as_uint(d));
            __threadfence();
            atomicAdd(&g_ebar, 1u);
            volatile unsigned* eb = &g_ebar;
            while (*eb < NB) __nanosleep(32);
            __threadfence();
            s_rr[0] = fmaxf(__uint_as_float(*(volatile unsigned*)&g_rmax[imgL]), 1.0f);
            s_rr[1] = fmaxf(__uint_as_float(*(volatile unsigned*)&g_rmin[imgL]), 1.0f);
            s_rr[2] = fmaxf(__uint_as_float(*(volatile unsigned*)&g_rmax[imgP]), 1.0f);
            s_rr[3] = fmaxf(__uint_as_float(*(volatile unsigned*)&g_rmin[imgP]), 1.0f);
        }
        __syncthreads();
    }
    const float rmaxL = s_rr[0], rminL = s_rr[1], rmaxP = s_rr[2], rminP = s_rr[3];
    const float irL = __fdividef(1.0f, rmaxL), irP = __fdividef(1.0f, rmaxP);

    // ---- q-maps + partial sums (register/shared data; pp from global) ----
    float t1 = 0.f, d1 = 0.f, t2 = 0.f, d2s = 0.f;
    #pragma unroll
    for (int k = 0; k < 8; k++) {
        int y = ybase + k;
        bool mL = (S.bits[0][y][wc0] >> shbit) & 1u;
        bool mP = (S.bits[1][y][wc0] >> shbit) & 1u;
        bool sL = (S.skelw[0][y] >> shbit) & 1u;
        bool sP = (S.skelw[1][y] >> shbit) & 1u;
        float dl = dm0[k], dp = dm1[k];
        float pp = g_pp[bat * 65536 + y * 256 + gc];

        float q_vl   = mL ? fminf(dl, rmaxL) * irL : 0.f;
        float q_slvl = sL ? dl * irL : 0.f;
        float q_sl   = sL ? (rmaxL - dl + rminL) * irL : 0.f;
        float q_vp   = mP ? fminf(dp, rmaxP) * irP * pp : 0.f;
        float q_spvp = sP ? dp * irP * pp : 0.f;
        float q_sp   = sP ? (rmaxP - dp + rminP) * irP * pp : 0.f;
        t1  += q_sp * q_vl;
        d1  += (sP && !sL) ? q_spvp * q_sp : q_slvl * q_sp;   // combine_tensors
        t2  += q_sl * q_vp;
        d2s += (sL && !sP) ? q_slvl * q_sl : q_spvp * q_sl;
    }
    #pragma unroll
    for (int o = 16; o; o >>= 1) {
        t1  += __shfl_xor_sync(0xffffffffu, t1,  o);
        d1  += __shfl_xor_sync(0xffffffffu, d1,  o);
        t2  += __shfl_xor_sync(0xffffffffu, t2,  o);
        d2s += __shfl_xor_sync(0xffffffffu, d2s, o);
    }
    if ((t & 31) == 0) {
        int w = t >> 5;
        s_red[0][w] = t1; s_red[1][w] = d1; s_red[2][w] = t2; s_red[3][w] = d2s;
    }
    __syncthreads();
    if (t == 0) {
        double a0 = 0.0, a1 = 0.0, a2 = 0.0, a3 = 0.0;
        #pragma unroll
        for (int w = 0; w < 8; w++) {
            a0 += (double)s_red[0][w]; a1 += (double)s_red[1][w];
            a2 += (double)s_red[2][w]; a3 += (double)s_red[3][w];
        }
        atomicAdd(&g_sums[0], a0);
        atomicAdd(&g_sums[1], a1);
        atomicAdd(&g_sums[2], a2);
        atomicAdd(&g_sums[3], a3);
        __threadfence();
        unsigned done = atomicAdd(&g_count, 1u);
        if (done == NB - 1) {                      // last block: epilogue + reset
            double S1 = atomicAdd(&g_sums[0], 0.0);
            double D1 = atomicAdd(&g_sums[1], 0.0);
            double S2 = atomicAdd(&g_sums[2], 0.0);
            double D2 = atomicAdd(&g_sums[3], 0.0);
            double wp = (S1 + 1.0) / (D1 + 1.0);
            double ws = (S2 + 1.0) / (D2 + 1.0);
            out[0] = (float)(1.0 - 2.0 * (wp * ws) / (wp + ws));
            // reset for graph replay
            g_bar1 = 0u; g_ebar = 0u; g_count = 0u;
            #pragma unroll
            for (int i = 0; i < 8; i++) { g_rmax[i] = 0u; g_rmin[i] = 0x7f7fffffu; }
            #pragma unroll
            for (int i = 0; i < 4; i++) g_sums[i] = 0.0;
            __threadfence();
        }
    }
}

// ---------------- launch ----------------
extern "C" void kernel_launch(void* const* d_in, const int* in_sizes, int n_in,
                              void* d_out, int out_size) {
    const float* ypred = (const float*)d_in[0];
    const int*   ytrue = (const int*)d_in[1];
    float*       out   = (float*)d_out;
    k_fused<<<NB, NT>>>(ypred, ytrue, out);
}

// round 7
// speedup vs baseline: 2.6255x; 1.1619x over previous
#include <cuda_runtime.h>
#include <math.h>

#define H 256
#define W 256
#define NW 8                 // 256 bits per row
#define NPIX (4*H*W)         // 262144
#define NB 128               // 4 batches x 32 col-tiles; co-resident on 148 SMs
#define NT 512

// ---------------- device state (reset by last block's epilogue) ----------------
__device__ float    g_pp[NPIX];
__device__ unsigned g_maskb[8][H][NW];
__device__ unsigned g_rmax[8];
__device__ unsigned g_rmin[8] = {0x7f7fffffu,0x7f7fffffu,0x7f7fffffu,0x7f7fffffu,
                                 0x7f7fffffu,0x7f7fffffu,0x7f7fffffu,0x7f7fffffu};
__device__ double   g_sums[4];
__device__ unsigned g_bar1;
__device__ unsigned g_ebar;
__device__ unsigned g_count;

__global__ void __launch_bounds__(NT) k_fused(const float* __restrict__ ypred,
                                              const int*   __restrict__ ytrue,
                                              float*       __restrict__ out) {
    __shared__ __align__(16) struct {
        unsigned bits[2][H][NW];                              // 16KB masks
        union {
            struct { unsigned ss[2][2][H][2]; unsigned sd[2][2][H][2]; } sk; // 32KB
            float shg[2][8][257];                                            // 16.4KB
        } u;
        unsigned skelw[2][H];                                 // 2KB tile-word skeleton
    } S;
    __shared__ float s_red[4][16];
    __shared__ float s_rr[4];

    const int t = threadIdx.x;

    // ================= Phase P: prep (2048 px per block, 4 px/thread) ========
    {
        int base = blockIdx.x * 2048 + t * 4;
        float4 x4 = *(const float4*)&ypred[base];
        int4   y4 = *(const int4*)&ytrue[base];
        float xs[4] = {x4.x, x4.y, x4.z, x4.w};
        float pps[4];
        #pragma unroll
        for (int q = 0; q < 4; q++) {
            float p = __fdividef(1.0f, 1.0f + __expf(-xs[q]));
            pps[q]  = __fdividef(1.0f, 1.0f + __expf(1.0f - 2.0f * p));
        }
        *(float4*)&g_pp[base] = make_float4(pps[0], pps[1], pps[2], pps[3]);

        unsigned nibP = (xs[0] > 0.f) | ((xs[1] > 0.f) << 1) | ((xs[2] > 0.f) << 2) | ((xs[3] > 0.f) << 3);
        unsigned nibT = (y4.x > 0) | ((y4.y > 0) << 1) | ((y4.z > 0) << 2) | ((y4.w > 0) << 3);
        int lane = t & 31;
        unsigned sh = (lane & 7) * 4;
        unsigned wP = nibP << sh, wT = nibT << sh;
        #pragma unroll
        for (int o = 1; o < 8; o <<= 1) {
            wP |= __shfl_xor_sync(0xffffffffu, wP, o);
            wT |= __shfl_xor_sync(0xffffffffu, wT, o);
        }
        if ((lane & 7) == 0) {
            int b = base >> 16, row = (base >> 8) & 255, word = (base & 255) >> 5;
            g_maskb[b * 2 + 0][row][word] = wT;
            g_maskb[b * 2 + 1][row][word] = wP;
        }
    }
    // ---- grid barrier 1 ----
    __syncthreads();
    if (t == 0) {
        __threadfence();
        atomicAdd(&g_bar1, 1u);
        volatile unsigned* vb = &g_bar1;
        while (*vb < NB) __nanosleep(32);
        __threadfence();
    }
    __syncthreads();

    // ================= Phase E: per (batch, 8-col tile) =================
    const int bat  = blockIdx.x >> 5;
    const int tile = blockIdx.x & 31;
    const int c0   = tile * 8;
    const int wc0  = c0 >> 5;
    const int imgL = bat * 2, imgP = bat * 2 + 1;

    {   // load both bitboards (vectorized; imgP contiguous after imgL)
        uint4* dst = (uint4*)&S.bits[0][0][0];
        const uint4* src = (const uint4*)&g_maskb[imgL][0][0];
        #pragma unroll
        for (int j = 0; j < 2; j++) dst[t + j * NT] = src[t + j * NT];
    }
    __syncthreads();

    // ---- band skeleton: img split across thread halves; 1 sync/iter ------
    {
        int wbs = (c0 - 12) < 0 ? 0 : ((c0 - 12) >> 5);
        const int wb = wbs > 6 ? 6 : wbs;
        const int tw = wc0 - wb;
        const int im = t >> 8;            // 0: true, 1: pred
        const int r  = t & 255;
        const int ru = r > 0 ? r - 1 : 0;
        const int rd = r < H - 1 ? r + 1 : H - 1;

        unsigned cur0 = S.bits[im][r][wb], cur1 = S.bits[im][r][wb + 1];
        unsigned sk0 = 0u, sk1 = 0u;
        S.u.sk.ss[0][im][r][0] = cur0;
        S.u.sk.ss[0][im][r][1] = cur1;
        __syncthreads();

        int b = 0;
        for (int it = 0; it < 11; it++) {
            unsigned vu0 = (r == 0)     ? 0xffffffffu : S.u.sk.ss[b][im][ru][0];
            unsigned vu1 = (r == 0)     ? 0xffffffffu : S.u.sk.ss[b][im][ru][1];
            unsigned vd0 = (r == H - 1) ? 0xffffffffu : S.u.sk.ss[b][im][rd][0];
            unsigned vd1 = (r == H - 1) ? 0xffffffffu : S.u.sk.ss[b][im][rd][1];
            unsigned sl0 = (cur0 << 1) | 1u;
            unsigned sl1 = (cur1 << 1) | (cur0 >> 31);
            unsigned sr0 = (cur0 >> 1) | (cur1 << 31);
            unsigned sr1 = (cur1 >> 1) | 0x80000000u;
            unsigned e0 = vu0 & vd0 & cur0 & sl0 & sr0;
            unsigned e1 = vu1 & vd1 & cur1 & sl1 & sr1;
            unsigned h0 = e0 | (e0 << 1) | (e0 >> 1) | (e1 << 31);
            unsigned h1 = e1 | (e1 << 1) | (e0 >> 31) | (e1 >> 1);
            S.u.sk.ss[b ^ 1][im][r][0] = e0;
            S.u.sk.ss[b ^ 1][im][r][1] = e1;
            S.u.sk.sd[b ^ 1][im][r][0] = h0;
            S.u.sk.sd[b ^ 1][im][r][1] = h1;
            __syncthreads();
            unsigned o0 = h0, o1 = h1;
            if (r > 0)     { o0 |= S.u.sk.sd[b ^ 1][im][ru][0]; o1 |= S.u.sk.sd[b ^ 1][im][ru][1]; }
            if (r < H - 1) { o0 |= S.u.sk.sd[b ^ 1][im][rd][0]; o1 |= S.u.sk.sd[b ^ 1][im][rd][1]; }
            sk0 |= cur0 & ~o0;
            sk1 |= cur1 & ~o1;
            cur0 = e0; cur1 = e1;
            b ^= 1;
        }
        S.skelw[im][r] = tw ? sk1 : sk0;
        __syncthreads();                           // skeleton done; shg may overlay
    }

    // ---- horizontal EDT via bit scans: thread = (image, row), 8 cols -------
    {
        const int im = t >> 8;
        const int r  = t & 255;
        #pragma unroll 1
        for (int k = 0; k < 8; k++) {
            int c = c0 + k, kk = c & 31;
            int dl = 512, dr = 512;
            unsigned v = ~S.bits[im][r][wc0] & (0xffffffffu >> (31 - kk));
            int w = wc0;
            while (true) { if (v) { dl = c - (w * 32 + 31 - __clz(v)); break; }
                           if (--w < 0) break; v = ~S.bits[im][r][w]; }
            v = ~S.bits[im][r][wc0] & (0xffffffffu << kk);
            w = wc0;
            while (true) { if (v) { dr = (w * 32 + __ffs(v) - 1) - c; break; }
                           if (++w >= NW) break; v = ~S.bits[im][r][w]; }
            int g = min(min(dl, dr), 512);
            S.u.shg[im][k][r] = (float)(g * g);
        }
    }
    __syncthreads();

    // ---- vertical envelope: 4 rows/thread, both images, spec unroll-4 ------
    const int c8    = t & 7;
    const int ybase = (t >> 3) * 4;
    const int gc    = c0 + c8;
    const unsigned shbit = gc & 31;
    const float* cp0 = &S.u.shg[0][c8][0];
    const float* cp1 = &S.u.shg[1][c8][0];
    float dm0[4], dm1[4];
    #pragma unroll 1
    for (int k = 0; k < 4; k++) {
        int y = ybase + k;
        float m0 = cp0[y], m1 = cp1[y];
        int dy = 1;
        while ((float)(dy * dy) < fmaxf(m0, m1) && dy < H) {
            #pragma unroll
            for (int j = 0; j < 4; j++) {          // clamped = safe overestimates
                int d = dy + j;
                float d2 = (float)(d * d);
                int ya = y - d; ya = ya < 0 ? 0 : ya;
                int yb = y + d; yb = yb > H - 1 ? H - 1 : yb;
                m0 = fminf(m0, fminf(cp0[ya], cp0[yb]) + d2);
                m1 = fminf(m1, fminf(cp1[ya], cp1[yb]) + d2);
            }
            dy += 4;
        }
        unsigned mb0 = (S.bits[0][y][wc0] >> shbit) & 1u;
        unsigned mb1 = (S.bits[1][y][wc0] >> shbit) & 1u;
        dm0[k] = mb0 ? sqrtf(m0) : 0.0f;
        dm1[k] = mb1 ? sqrtf(m1) : 0.0f;
    }

    // ---- tile rmax/rmin for both images + global barrier ----
    {
        float mxL = 0.f, mnL = __int_as_float(0x7f7fffff);
        float mxP = 0.f, mnP = __int_as_float(0x7f7fffff);
        #pragma unroll
        for (int k = 0; k < 4; k++) {
            int y = ybase + k;
            float srL = ((S.skelw[0][y] >> shbit) & 1u) ? dm0[k] : 0.f;
            float srP = ((S.skelw[1][y] >> shbit) & 1u) ? dm1[k] : 0.f;
            mxL = fmaxf(mxL, srL); mnL = fminf(mnL, srL);
            mxP = fmaxf(mxP, srP); mnP = fminf(mnP, srP);
        }
        #pragma unroll
        for (int o = 16; o; o >>= 1) {
            mxL = fmaxf(mxL, __shfl_xor_sync(0xffffffffu, mxL, o));
            mnL = fminf(mnL, __shfl_xor_sync(0xffffffffu, mnL, o));
            mxP = fmaxf(mxP, __shfl_xor_sync(0xffffffffu, mxP, o));
            mnP = fminf(mnP, __shfl_xor_sync(0xffffffffu, mnP, o));
        }
        if ((t & 31) == 0) {
            int w = t >> 5;
            s_red[0][w] = mxL; s_red[1][w] = mnL; s_red[2][w] = mxP; s_red[3][w] = mnP;
        }
        __syncthreads();
        if (t == 0) {
            float a = s_red[0][0], b = s_red[1][0], c = s_red[2][0], d = s_red[3][0];
            #pragma unroll
            for (int w = 1; w < 16; w++) {
                a = fmaxf(a, s_red[0][w]); b = fminf(b, s_red[1][w]);
                c = fmaxf(c, s_red[2][w]); d = fminf(d, s_red[3][w]);
            }
            atomicMax(&g_rmax[imgL], __float_as_uint(a));
            atomicMin(&g_rmin[imgL], __float_as_uint(b));
            atomicMax(&g_rmax[imgP], __float_as_uint(c));
            atomicMin(&g_rmin[imgP], __float_as_uint(d));
            __threadfence();
            atomicAdd(&g_ebar, 1u);
            volatile unsigned* eb = &g_ebar;
            while (*eb < NB) __nanosleep(32);
            __threadfence();
            s_rr[0] = fmaxf(__uint_as_float(*(volatile unsigned*)&g_rmax[imgL]), 1.0f);
            s_rr[1] = fmaxf(__uint_as_float(*(volatile unsigned*)&g_rmin[imgL]), 1.0f);
            s_rr[2] = fmaxf(__uint_as_float(*(volatile unsigned*)&g_rmax[imgP]), 1.0f);
            s_rr[3] = fmaxf(__uint_as_float(*(volatile unsigned*)&g_rmin[imgP]), 1.0f);
        }
        __syncthreads();
    }
    const float rmaxL = s_rr[0], rminL = s_rr[1], rmaxP = s_rr[2], rminP = s_rr[3];
    const float irL = __fdividef(1.0f, rmaxL), irP = __fdividef(1.0f, rmaxP);

    // ---- q-maps + partial sums ----
    float t1 = 0.f, d1 = 0.f, t2 = 0.f, d2s = 0.f;
    #pragma unroll
    for (int k = 0; k < 4; k++) {
        int y = ybase + k;
        bool mL = (S.bits[0][y][wc0] >> shbit) & 1u;
        bool mP = (S.bits[1][y][wc0] >> shbit) & 1u;
        bool sL = (S.skelw[0][y] >> shbit) & 1u;
        bool sP = (S.skelw[1][y] >> shbit) & 1u;
        float dl = dm0[k], dp = dm1[k];
        float pp = g_pp[bat * 65536 + y * 256 + gc];

        float q_vl   = mL ? fminf(dl, rmaxL) * irL : 0.f;
        float q_slvl = sL ? dl * irL : 0.f;
        float q_sl   = sL ? (rmaxL - dl + rminL) * irL : 0.f;
        float q_vp   = mP ? fminf(dp, rmaxP) * irP * pp : 0.f;
        float q_spvp = sP ? dp * irP * pp : 0.f;
        float q_sp   = sP ? (rmaxP - dp + rminP) * irP * pp : 0.f;
        t1  += q_sp * q_vl;
        d1  += (sP && !sL) ? q_spvp * q_sp : q_slvl * q_sp;   // combine_tensors
        t2  += q_sl * q_vp;
        d2s += (sL && !sP) ? q_slvl * q_sl : q_spvp * q_sl;
    }
    #pragma unroll
    for (int o = 16; o; o >>= 1) {
        t1  += __shfl_xor_sync(0xffffffffu, t1,  o);
        d1  += __shfl_xor_sync(0xffffffffu, d1,  o);
        t2  += __shfl_xor_sync(0xffffffffu, t2,  o);
        d2s += __shfl_xor_sync(0xffffffffu, d2s, o);
    }
    if ((t & 31) == 0) {
        int w = t >> 5;
        s_red[0][w] = t1; s_red[1][w] = d1; s_red[2][w] = t2; s_red[3][w] = d2s;
    }
    __syncthreads();
    if (t == 0) {
        double a0 = 0.0, a1 = 0.0, a2 = 0.0, a3 = 0.0;
        #pragma unroll
        for (int w = 0; w < 16; w++) {
            a0 += (double)s_red[0][w]; a1 += (double)s_red[1][w];
            a2 += (double)s_red[2][w]; a3 += (double)s_red[3][w];
        }
        atomicAdd(&g_sums[0], a0);
        atomicAdd(&g_sums[1], a1);
        atomicAdd(&g_sums[2], a2);
        atomicAdd(&g_sums[3], a3);
        __threadfence();
        unsigned done = atomicAdd(&g_count, 1u);
        if (done == NB - 1) {                      // last block: epilogue + reset
            double S1 = atomicAdd(&g_sums[0], 0.0);
            double D1 = atomicAdd(&g_sums[1], 0.0);
            double S2 = atomicAdd(&g_sums[2], 0.0);
            double D2 = atomicAdd(&g_sums[3], 0.0);
            double wp = (S1 + 1.0) / (D1 + 1.0);
            double ws = (S2 + 1.0) / (D2 + 1.0);
            out[0] = (float)(1.0 - 2.0 * (wp * ws) / (wp + ws));
            g_bar1 = 0u; g_ebar = 0u; g_count = 0u;
            #pragma unroll
            for (int i = 0; i < 8; i++) { g_rmax[i] = 0u; g_rmin[i] = 0x7f7fffffu; }
            #pragma unroll
            for (int i = 0; i < 4; i++) g_sums[i] = 0.0;
            __threadfence();
        }
    }
}

// ---------------- launch ----------------
extern "C" void kernel_launch(void* const* d_in, const int* in_sizes, int n_in,
                              void* d_out, int out_size) {
    const float* ypred = (const float*)d_in[0];
    const int*   ytrue = (const int*)d_in[1];
    float*       out   = (float*)d_out;
    k_fused<<<NB, NT>>>(ypred, ytrue, out);
}